// round 1
// baseline (speedup 1.0000x reference)
#include <cuda_runtime.h>
#include <math.h>

#define NTOK  4096
#define HID   1024
#define INTER 2048
#define NEXP  8
#define TOPK  2
#define NSLOT (NTOK * TOPK)

#define BM 64
#define BN 64
#define BK 16

// ---------------- device scratch (static; no allocations allowed) ----------------
__device__ int   d_counts[NEXP];
__device__ int   d_offsets[NEXP];
__device__ int   d_cursor[NEXP];
__device__ float d_prob_sum[NEXP];
__device__ int   d_gate_e[NTOK * TOPK];
__device__ float d_gate_w[NTOK * TOPK];
__device__ int   d_tok[NSLOT];
__device__ float d_tw[NSLOT];
__device__ float d_h[(size_t)NSLOT * INTER];   // 8192 x 2048 fp32 = 64 MB

// ---------------- small init ----------------
__global__ void zero_small_kernel() {
    int t = threadIdx.x;
    if (t < NEXP) {
        d_counts[t] = 0;
        d_prob_sum[t] = 0.f;
    }
}

__global__ void zero_out_kernel(float* __restrict__ out, int n) {
    int i = blockIdx.x * blockDim.x + threadIdx.x;
    if (i < n) out[i] = 0.f;
}

// ---------------- router: logits, softmax, top-2, counts, prob sums ----------------
// 8 warps/block, 1 token per warp.
__global__ void router_kernel(const float* __restrict__ x, const float* __restrict__ rw) {
    int warp = threadIdx.x >> 5;
    int lane = threadIdx.x & 31;
    int n = blockIdx.x * 8 + warp;

    __shared__ float s_prob[NEXP];
    __shared__ int   s_cnt[NEXP];
    if (threadIdx.x < NEXP) { s_prob[threadIdx.x] = 0.f; s_cnt[threadIdx.x] = 0; }
    __syncthreads();

    float acc[NEXP];
#pragma unroll
    for (int e = 0; e < NEXP; e++) acc[e] = 0.f;

    const float* xr = x + (size_t)n * HID;
    for (int h = lane; h < HID; h += 32) {
        float xv = xr[h];
#pragma unroll
        for (int e = 0; e < NEXP; e++) acc[e] += xv * rw[e * HID + h];
    }
#pragma unroll
    for (int e = 0; e < NEXP; e++) {
#pragma unroll
        for (int s = 16; s > 0; s >>= 1)
            acc[e] += __shfl_down_sync(0xffffffffu, acc[e], s);
    }

    if (lane == 0) {
        float mx = acc[0];
#pragma unroll
        for (int e = 1; e < NEXP; e++) mx = fmaxf(mx, acc[e]);
        float p[NEXP];
        float sum = 0.f;
#pragma unroll
        for (int e = 0; e < NEXP; e++) { p[e] = expf(acc[e] - mx); sum += p[e]; }
        float inv = 1.f / sum;
#pragma unroll
        for (int e = 0; e < NEXP; e++) p[e] *= inv;

        // top-2 (ties -> lowest index, matches jax top_k)
        int b0 = 0;
#pragma unroll
        for (int e = 1; e < NEXP; e++) if (p[e] > p[b0]) b0 = e;
        int b1 = (b0 == 0) ? 1 : 0;
#pragma unroll
        for (int e = 0; e < NEXP; e++) if (e != b0 && p[e] > p[b1]) b1 = e;

        float w0 = p[b0], w1 = p[b1];
        float winv = 1.f / (w0 + w1);
        d_gate_e[n * 2 + 0] = b0;
        d_gate_e[n * 2 + 1] = b1;
        d_gate_w[n * 2 + 0] = w0 * winv;
        d_gate_w[n * 2 + 1] = w1 * winv;

        atomicAdd(&s_cnt[b0], 1);
        atomicAdd(&s_cnt[b1], 1);
#pragma unroll
        for (int e = 0; e < NEXP; e++) atomicAdd(&s_prob[e], p[e]);
    }
    __syncthreads();
    if (threadIdx.x < NEXP) {
        atomicAdd(&d_counts[threadIdx.x], s_cnt[threadIdx.x]);
        atomicAdd(&d_prob_sum[threadIdx.x], s_prob[threadIdx.x]);
    }
}

// ---------------- exclusive scan over 8 counts ----------------
__global__ void scan_kernel() {
    int o = 0;
#pragma unroll
    for (int e = 0; e < NEXP; e++) {
        d_offsets[e] = o;
        d_cursor[e]  = o;
        o += d_counts[e];
    }
}

// ---------------- scatter tokens into per-expert segments ----------------
__global__ void scatter_kernel() {
    int n = blockIdx.x * blockDim.x + threadIdx.x;
    if (n >= NTOK) return;
#pragma unroll
    for (int j = 0; j < TOPK; j++) {
        int e = d_gate_e[n * 2 + j];
        int pos = atomicAdd(&d_cursor[e], 1);
        d_tok[pos] = n;
        d_tw[pos]  = d_gate_w[n * 2 + j];
    }
}

// ---------------- up-projection GEMM + GELU (gate weight folded in) ----------------
// grid: (INTER/BN, NTOK/BM, NEXP), 256 threads
__global__ void up_kernel(const float* __restrict__ x, const float* __restrict__ up_w) {
    int e   = blockIdx.z;
    int cnt = d_counts[e];
    int m0  = blockIdx.y * BM;
    if (m0 >= cnt) return;
    int f0  = blockIdx.x * BN;
    int off = d_offsets[e];

    __shared__ float As[BK][BM + 1];
    __shared__ float Bs[BK][BN + 1];
    __shared__ int   toks[BM];
    __shared__ float tws[BM];

    int tid = threadIdx.x;
    if (tid < BM) {
        int mg = m0 + tid;
        if (mg < cnt) { toks[tid] = d_tok[off + mg]; tws[tid] = d_tw[off + mg]; }
        else          { toks[tid] = -1;              tws[tid] = 0.f; }
    }
    __syncthreads();

    int tr = tid >> 4, tc = tid & 15;
    float acc[4][4];
#pragma unroll
    for (int i = 0; i < 4; i++)
#pragma unroll
        for (int j = 0; j < 4; j++) acc[i][j] = 0.f;

    const float* wB = up_w + (size_t)e * HID * INTER;

    for (int k0 = 0; k0 < HID; k0 += BK) {
#pragma unroll
        for (int j = 0; j < 4; j++) {
            int idx = tid + j * 256;
            int m = idx >> 4, k = idx & 15;
            int t = toks[m];
            As[k][m] = (t >= 0) ? x[(size_t)t * HID + k0 + k] : 0.f;
        }
#pragma unroll
        for (int j = 0; j < 4; j++) {
            int idx = tid + j * 256;
            int k = idx >> 6, f = idx & 63;
            Bs[k][f] = wB[(size_t)(k0 + k) * INTER + f0 + f];
        }
        __syncthreads();
#pragma unroll
        for (int k = 0; k < BK; k++) {
            float a[4], b[4];
#pragma unroll
            for (int i = 0; i < 4; i++) a[i] = As[k][tr * 4 + i];
#pragma unroll
            for (int i = 0; i < 4; i++) b[i] = Bs[k][tc * 4 + i];
#pragma unroll
            for (int i = 0; i < 4; i++)
#pragma unroll
                for (int j = 0; j < 4; j++) acc[i][j] += a[i] * b[j];
        }
        __syncthreads();
    }

#pragma unroll
    for (int i = 0; i < 4; i++) {
        int m = tr * 4 + i;
        if (m0 + m < cnt) {
            float w = tws[m];
            size_t base = (size_t)(off + m0 + m) * INTER + f0 + tc * 4;
#pragma unroll
            for (int j = 0; j < 4; j++) {
                float v = acc[i][j];
                float g = 0.5f * v * (1.0f + erff(v * 0.70710678118654752f));
                d_h[base + j] = w * g;
            }
        }
    }
}

// ---------------- down-projection GEMM, atomic accumulate into output ----------------
// grid: (HID/BN, NTOK/BM, NEXP), 256 threads
__global__ void down_kernel(const float* __restrict__ down_w, float* __restrict__ out) {
    int e   = blockIdx.z;
    int cnt = d_counts[e];
    int m0  = blockIdx.y * BM;
    if (m0 >= cnt) return;
    int h0  = blockIdx.x * BN;
    int off = d_offsets[e];

    __shared__ float As[BK][BM + 1];
    __shared__ float Bs[BK][BN + 1];
    __shared__ int   toks[BM];

    int tid = threadIdx.x;
    if (tid < BM) {
        int mg = m0 + tid;
        toks[tid] = (mg < cnt) ? d_tok[off + mg] : -1;
    }
    __syncthreads();

    int tr = tid >> 4, tc = tid & 15;
    float acc[4][4];
#pragma unroll
    for (int i = 0; i < 4; i++)
#pragma unroll
        for (int j = 0; j < 4; j++) acc[i][j] = 0.f;

    const float* wB = down_w + (size_t)e * INTER * HID;

    for (int k0 = 0; k0 < INTER; k0 += BK) {
#pragma unroll
        for (int j = 0; j < 4; j++) {
            int idx = tid + j * 256;
            int m = idx >> 4, k = idx & 15;
            int mg = m0 + m;
            As[k][m] = (mg < cnt) ? d_h[(size_t)(off + mg) * INTER + k0 + k] : 0.f;
        }
#pragma unroll
        for (int j = 0; j < 4; j++) {
            int idx = tid + j * 256;
            int k = idx >> 6, h = idx & 63;
            Bs[k][h] = wB[(size_t)(k0 + k) * HID + h0 + h];
        }
        __syncthreads();
#pragma unroll
        for (int k = 0; k < BK; k++) {
            float a[4], b[4];
#pragma unroll
            for (int i = 0; i < 4; i++) a[i] = As[k][tr * 4 + i];
#pragma unroll
            for (int i = 0; i < 4; i++) b[i] = Bs[k][tc * 4 + i];
#pragma unroll
            for (int i = 0; i < 4; i++)
#pragma unroll
                for (int j = 0; j < 4; j++) acc[i][j] += a[i] * b[j];
        }
        __syncthreads();
    }

#pragma unroll
    for (int i = 0; i < 4; i++) {
        int m = tr * 4 + i;
        if (m0 + m < cnt) {
            int t = toks[m];
            size_t base = (size_t)t * HID + h0 + tc * 4;
#pragma unroll
            for (int j = 0; j < 4; j++)
                atomicAdd(&out[base + j], acc[i][j]);
        }
    }
}

// ---------------- aux loss ----------------
__global__ void aux_kernel(float* __restrict__ out_aux) {
    float a = 0.f;
#pragma unroll
    for (int e = 0; e < NEXP; e++) {
        float f = (float)d_counts[e] / (float)(NTOK * TOPK);
        float P = d_prob_sum[e] / (float)NTOK;
        a += f * P;
    }
    *out_aux = (float)NEXP * a;
}

// ---------------- launch ----------------
extern "C" void kernel_launch(void* const* d_in, const int* in_sizes, int n_in,
                              void* d_out, int out_size) {
    const float* x      = (const float*)d_in[0];
    const float* rw     = (const float*)d_in[1];
    const float* up_w   = (const float*)d_in[2];
    const float* down_w = (const float*)d_in[3];
    float* out = (float*)d_out;

    zero_small_kernel<<<1, 32>>>();
    zero_out_kernel<<<(NTOK * HID + 255) / 256, 256>>>(out, NTOK * HID);
    router_kernel<<<NTOK / 8, 256>>>(x, rw);
    scan_kernel<<<1, 1>>>();
    scatter_kernel<<<(NTOK + 255) / 256, 256>>>();

    dim3 gu(INTER / BN, NTOK / BM, NEXP);
    up_kernel<<<gu, 256>>>(x, up_w);

    dim3 gd(HID / BN, NTOK / BM, NEXP);
    down_kernel<<<gd, 256>>>(down_w, out);

    if (out_size > NTOK * HID) {
        aux_kernel<<<1, 1>>>(out + NTOK * HID);
    }
}

// round 4
// speedup vs baseline: 4.8667x; 4.8667x over previous
#include <cuda_runtime.h>
#include <math.h>
#include <stdint.h>

#define NTOK  4096
#define HID   1024
#define INTER 2048
#define NEXP  8
#define TOPK  2
#define NSLOT (NTOK*TOPK)
#define PAD   128

// smem strides (floats), padded for conflict-free fragment loads
#define ASTRIDE 36     // 32 k + 4 pad   -> bank (4r+c)%32 distinct
#define BSTRIDE 136    // 128 n + 8 pad  -> bank (8k+u)%32 distinct
#define ABYTES  (128*ASTRIDE*4)   // 18432
#define BBYTES  (32*BSTRIDE*4)    // 17408
#define BUFBYTES (ABYTES+BBYTES)  // 35840
#define BUFFLOATS (BUFBYTES/4)    // 8960
#define SMEM_TOTAL (2*BUFBYTES)   // 71680

// ---------------- device scratch ----------------
__device__ int   d_counts[NEXP];
__device__ int   d_offsets[NEXP];
__device__ int   d_cursor[NEXP];
__device__ float d_prob_sum[NEXP];
__device__ int   d_gate_e[NTOK*TOPK];
__device__ float d_gate_w[NTOK*TOPK];
__device__ int   d_slot[NTOK*TOPK];
__device__ int   d_tok[NSLOT];
__device__ float d_tw[NSLOT];
// pad rows beyond NSLOT are never written -> stay zero from load-time init
__device__ float d_ax[(size_t)(NSLOT+PAD)*HID];
__device__ float d_hbuf[(size_t)(NSLOT+PAD)*INTER];
__device__ float d_y[(size_t)(NSLOT+PAD)*HID];

// ---------------- helpers ----------------
__device__ __forceinline__ float tf32r(float v){
    uint32_t o; asm("cvt.rna.tf32.f32 %0, %1;":"=r"(o):"f"(v));
    return __uint_as_float(o);
}
__device__ __forceinline__ void cpasync16(uint32_t dst, const void* src){
    asm volatile("cp.async.cg.shared.global [%0], [%1], 16;"::"r"(dst),"l"(src));
}
__device__ __forceinline__ void cp_commit(){ asm volatile("cp.async.commit_group;"); }
__device__ __forceinline__ void cp_wait1(){ asm volatile("cp.async.wait_group 1;"); }
__device__ __forceinline__ void cp_wait0(){ asm volatile("cp.async.wait_group 0;"); }
__device__ __forceinline__ uint32_t smem_u32(const void* p){
    uint32_t a;
    asm("{ .reg .u64 t; cvta.to.shared.u64 t, %1; cvt.u32.u64 %0, t; }":"=r"(a):"l"(p));
    return a;
}
__device__ __forceinline__ void mma_tf32(float c[4], uint32_t a0, uint32_t a1,
                                         uint32_t a2, uint32_t a3,
                                         uint32_t b0, uint32_t b1){
    asm volatile(
        "mma.sync.aligned.m16n8k8.row.col.f32.tf32.tf32.f32 "
        "{%0,%1,%2,%3}, {%4,%5,%6,%7}, {%8,%9}, {%0,%1,%2,%3};"
        : "+f"(c[0]),"+f"(c[1]),"+f"(c[2]),"+f"(c[3])
        : "r"(a0),"r"(a1),"r"(a2),"r"(a3),"r"(b0),"r"(b1));
}

// ---------------- small kernels ----------------
__global__ void zero_small_kernel(){
    int t = threadIdx.x;
    if (t < NEXP){ d_counts[t]=0; d_prob_sum[t]=0.f; }
}

__global__ void router_kernel(const float* __restrict__ x, const float* __restrict__ rw){
    int warp = threadIdx.x >> 5;
    int lane = threadIdx.x & 31;
    int n = blockIdx.x * 8 + warp;

    __shared__ float s_prob[NEXP];
    __shared__ int   s_cnt[NEXP];
    if (threadIdx.x < NEXP){ s_prob[threadIdx.x]=0.f; s_cnt[threadIdx.x]=0; }
    __syncthreads();

    float acc[NEXP];
#pragma unroll
    for (int e=0;e<NEXP;e++) acc[e]=0.f;
    const float* xr = x + (size_t)n*HID;
    for (int h=lane; h<HID; h+=32){
        float xv = xr[h];
#pragma unroll
        for (int e=0;e<NEXP;e++) acc[e] += xv*rw[e*HID+h];
    }
#pragma unroll
    for (int e=0;e<NEXP;e++){
#pragma unroll
        for (int s=16;s>0;s>>=1) acc[e] += __shfl_down_sync(0xffffffffu, acc[e], s);
    }
    if (lane==0){
        float mx = acc[0];
#pragma unroll
        for (int e=1;e<NEXP;e++) mx = fmaxf(mx, acc[e]);
        float p[NEXP]; float sum=0.f;
#pragma unroll
        for (int e=0;e<NEXP;e++){ p[e]=expf(acc[e]-mx); sum+=p[e]; }
        float inv = 1.f/sum;
#pragma unroll
        for (int e=0;e<NEXP;e++) p[e]*=inv;
        int b0=0;
#pragma unroll
        for (int e=1;e<NEXP;e++) if (p[e]>p[b0]) b0=e;
        int b1 = (b0==0)?1:0;
#pragma unroll
        for (int e=0;e<NEXP;e++) if (e!=b0 && p[e]>p[b1]) b1=e;
        float w0=p[b0], w1=p[b1], winv=1.f/(w0+w1);
        d_gate_e[n*2+0]=b0; d_gate_e[n*2+1]=b1;
        d_gate_w[n*2+0]=w0*winv; d_gate_w[n*2+1]=w1*winv;
        atomicAdd(&s_cnt[b0],1); atomicAdd(&s_cnt[b1],1);
#pragma unroll
        for (int e=0;e<NEXP;e++) atomicAdd(&s_prob[e], p[e]);
    }
    __syncthreads();
    if (threadIdx.x < NEXP){
        atomicAdd(&d_counts[threadIdx.x], s_cnt[threadIdx.x]);
        atomicAdd(&d_prob_sum[threadIdx.x], s_prob[threadIdx.x]);
    }
}

__global__ void scan_kernel(){
    int o=0;
#pragma unroll
    for (int e=0;e<NEXP;e++){ d_offsets[e]=o; d_cursor[e]=o; o+=d_counts[e]; }
}

__global__ void scatter_kernel(){
    int n = blockIdx.x*blockDim.x + threadIdx.x;
    if (n >= NTOK) return;
#pragma unroll
    for (int j=0;j<TOPK;j++){
        int e = d_gate_e[n*2+j];
        int pos = atomicAdd(&d_cursor[e], 1);
        d_tok[pos]=n; d_tw[pos]=d_gate_w[n*2+j];
        d_slot[n*2+j]=pos;
    }
}

// gather tokens into contiguous per-expert rows (tf32 rna rounding)
__global__ void gather_kernel(const float* __restrict__ x){
    int s = blockIdx.x;
    int t = d_tok[s];
    const float4* src = (const float4*)(x + (size_t)t*HID);
    float4* dst = (float4*)(d_ax + (size_t)s*HID);
    float4 v = src[threadIdx.x];
    v.x=tf32r(v.x); v.y=tf32r(v.y); v.z=tf32r(v.z); v.w=tf32r(v.w);
    dst[threadIdx.x] = v;
}

// ---------------- mma.sync tf32 grouped GEMM ----------------
// C[128,128] per CTA. A = slot rows [m][k] (k-major). B = weights [k][n] (n contiguous).
// 8 warps: 2 (m) x 4 (n); warp tile 64x32; 4x4 m16n8k8 fragments.
// GELU_W: up-proj epilogue (gate-weighted exact GELU, tf32-rounded into d_hbuf).
template<int KTOT, int NFULL, bool GELU_W>
__global__ void __launch_bounds__(256,2) moe_gemm_kernel(
        const float* __restrict__ Wg){
    constexpr int NK = KTOT/32;
    int e   = blockIdx.z;
    int cnt = d_counts[e];
    int m0  = blockIdx.y*128;
    if (m0 >= cnt) return;
    int off = d_offsets[e];
    int n0  = blockIdx.x*128;

    extern __shared__ float smem[];
    uint32_t sb = smem_u32(smem);
    int tid = threadIdx.x;
    int wid = tid>>5, lane = tid&31;
    int wm = wid>>2, wn = wid&3;
    int qrow = lane>>2, qcol = lane&3;

    const float* A_ = GELU_W ? d_ax : d_hbuf;
    const float* Arow = A_ + (size_t)(off+m0)*KTOT;
    const float* Bgl  = Wg + (size_t)e*KTOT*NFULL + n0;

    // per-thread load slots (4 x 16B for A tile, 4 x 16B for B tile)
    int arow[4], aq[4], bk[4], bq[4];
#pragma unroll
    for (int t=0;t<4;t++){
        int idx = tid + t*256;
        arow[t] = idx>>3;  aq[t] = idx&7;    // 128 rows x 8 chunks
        bk[t]   = idx>>5;  bq[t] = idx&31;   // 32 k-rows x 32 chunks
    }

    auto load_chunk = [&](int kc, int b){
        int k0 = kc*32;
        uint32_t ab = sb + b*BUFBYTES;
        uint32_t bb = ab + ABYTES;
#pragma unroll
        for (int t=0;t<4;t++){
            cpasync16(ab + arow[t]*(ASTRIDE*4) + aq[t]*16,
                      Arow + (size_t)arow[t]*KTOT + k0 + aq[t]*4);
            cpasync16(bb + bk[t]*(BSTRIDE*4) + bq[t]*16,
                      Bgl + (size_t)(k0+bk[t])*NFULL + bq[t]*4);
        }
    };

    float acc[4][4][4];
#pragma unroll
    for (int i=0;i<4;i++)
#pragma unroll
        for (int j=0;j<4;j++)
#pragma unroll
            for (int q=0;q<4;q++) acc[i][j][q]=0.f;

    load_chunk(0,0); cp_commit();
    for (int kc=0; kc<NK; kc++){
        int b = kc&1;
        if (kc+1 < NK){ load_chunk(kc+1, b^1); cp_commit(); cp_wait1(); }
        else          { cp_wait0(); }
        __syncthreads();

        const float* as = smem + b*BUFFLOATS;
        const float* bs = as + ABYTES/4;
#pragma unroll
        for (int kk=0; kk<4; kk++){
            int k = kk*8;
            uint32_t afr[4][4];
#pragma unroll
            for (int mt=0; mt<4; mt++){
                int r = wm*64 + mt*16 + qrow;
                afr[mt][0] = __float_as_uint(as[(r  )*ASTRIDE + k + qcol    ]);
                afr[mt][1] = __float_as_uint(as[(r+8)*ASTRIDE + k + qcol    ]);
                afr[mt][2] = __float_as_uint(as[(r  )*ASTRIDE + k + qcol + 4]);
                afr[mt][3] = __float_as_uint(as[(r+8)*ASTRIDE + k + qcol + 4]);
            }
            uint32_t bfr[4][2];
#pragma unroll
            for (int nt=0; nt<4; nt++){
                int n = wn*32 + nt*8 + qrow;
                bfr[nt][0] = __float_as_uint(bs[(k+qcol  )*BSTRIDE + n]);
                bfr[nt][1] = __float_as_uint(bs[(k+qcol+4)*BSTRIDE + n]);
            }
#pragma unroll
            for (int mt=0; mt<4; mt++)
#pragma unroll
                for (int nt=0; nt<4; nt++)
                    mma_tf32(acc[mt][nt],
                             afr[mt][0],afr[mt][1],afr[mt][2],afr[mt][3],
                             bfr[nt][0],bfr[nt][1]);
        }
        __syncthreads();
    }

    // ---------------- epilogue ----------------
#pragma unroll
    for (int mt=0; mt<4; mt++){
#pragma unroll
        for (int half=0; half<2; half++){
            int row = wm*64 + mt*16 + qrow + half*8;
            if (m0+row >= cnt) continue;
            int slot = off + m0 + row;
            if (GELU_W){
                float gw = d_tw[slot];
                float* orow = d_hbuf + (size_t)slot*NFULL + n0;
#pragma unroll
                for (int nt=0; nt<4; nt++){
                    int col = wn*32 + nt*8 + qcol*2;
                    float v0 = acc[mt][nt][half*2+0];
                    float v1 = acc[mt][nt][half*2+1];
                    v0 = tf32r(gw * 0.5f * v0 * (1.0f + erff(v0*0.70710678118654752f)));
                    v1 = tf32r(gw * 0.5f * v1 * (1.0f + erff(v1*0.70710678118654752f)));
                    *(float2*)(orow + col) = make_float2(v0, v1);
                }
            } else {
                float* orow = d_y + (size_t)slot*NFULL + n0;
#pragma unroll
                for (int nt=0; nt<4; nt++){
                    int col = wn*32 + nt*8 + qcol*2;
                    *(float2*)(orow + col) =
                        make_float2(acc[mt][nt][half*2+0], acc[mt][nt][half*2+1]);
                }
            }
        }
    }
}

// out[n] = y[slot0] + y[slot1]
__global__ void combine_kernel(float* __restrict__ out){
    int n = blockIdx.x;
    int s0 = d_slot[n*2+0], s1 = d_slot[n*2+1];
    const float4* a = (const float4*)(d_y + (size_t)s0*HID);
    const float4* b = (const float4*)(d_y + (size_t)s1*HID);
    float4* o = (float4*)(out + (size_t)n*HID);
    float4 va = a[threadIdx.x], vb = b[threadIdx.x];
    o[threadIdx.x] = make_float4(va.x+vb.x, va.y+vb.y, va.z+vb.z, va.w+vb.w);
}

__global__ void aux_kernel(float* __restrict__ out_aux){
    float a=0.f;
#pragma unroll
    for (int e=0;e<NEXP;e++){
        float f = (float)d_counts[e] / (float)(NTOK*TOPK);
        float P = d_prob_sum[e] / (float)NTOK;
        a += f*P;
    }
    *out_aux = (float)NEXP*a;
}

// ---------------- launch ----------------
extern "C" void kernel_launch(void* const* d_in, const int* in_sizes, int n_in,
                              void* d_out, int out_size){
    const float* x      = (const float*)d_in[0];
    const float* rw     = (const float*)d_in[1];
    const float* up_w   = (const float*)d_in[2];
    const float* down_w = (const float*)d_in[3];
    float* out = (float*)d_out;

    cudaFuncSetAttribute(moe_gemm_kernel<HID,INTER,true>,
                         cudaFuncAttributeMaxDynamicSharedMemorySize, SMEM_TOTAL);
    cudaFuncSetAttribute(moe_gemm_kernel<INTER,HID,false>,
                         cudaFuncAttributeMaxDynamicSharedMemorySize, SMEM_TOTAL);

    zero_small_kernel<<<1,32>>>();
    router_kernel<<<NTOK/8,256>>>(x, rw);
    scan_kernel<<<1,1>>>();
    scatter_kernel<<<(NTOK+255)/256,256>>>();
    gather_kernel<<<NSLOT,256>>>(x);

    moe_gemm_kernel<HID,INTER,true>
        <<<dim3(INTER/128, NSLOT/128, NEXP), 256, SMEM_TOTAL>>>(up_w);
    moe_gemm_kernel<INTER,HID,false>
        <<<dim3(HID/128, NSLOT/128, NEXP), 256, SMEM_TOTAL>>>(down_w);

    combine_kernel<<<NTOK,256>>>(out);
    if (out_size > NTOK*HID) aux_kernel<<<1,1>>>(out + NTOK*HID);
}